// round 10
// baseline (speedup 1.0000x reference)
#include <cuda_runtime.h>
#include <cuda_fp16.h>

#define SMEM_BYTES 209408

namespace {

constexpr int THsz = 1536;

// ---------- device scratch ----------
__device__ __half   g_wpack[3][786432];   // packed B-frags per gemm
__device__ float    g_yctr[512 * THsz];   // y@w_ih1[:,1:]^T + b_ih1
__device__ __half   g_s0h[2][512 * 512];
__device__ __half   g_s1h[2][512 * 512];
__device__ float    g_fcpart[512 * 32];
__device__ unsigned g_bar[4096];          // 4 groups x 1024 slots

// ---------- helpers ----------
__device__ __forceinline__ unsigned su32(const void* p) {
  return (unsigned)__cvta_generic_to_shared(p);
}
__device__ __forceinline__ void cp16(unsigned d, const void* s) {
  asm volatile("cp.async.cg.shared.global [%0], [%1], 16;\n" :: "r"(d), "l"(s));
}
__device__ __forceinline__ void cpcommit() { asm volatile("cp.async.commit_group;\n"); }
template <int N> __device__ __forceinline__ void cpwait() {
  asm volatile("cp.async.wait_group %0;\n" :: "n"(N));
}
__device__ __forceinline__ void ldsm4(unsigned& r0, unsigned& r1, unsigned& r2,
                                      unsigned& r3, unsigned a) {
  asm volatile("ldmatrix.sync.aligned.m8n8.x4.shared.b16 {%0,%1,%2,%3}, [%4];\n"
               : "=r"(r0), "=r"(r1), "=r"(r2), "=r"(r3) : "r"(a));
}
__device__ __forceinline__ void mma16816(float* c, unsigned a0, unsigned a1,
                                         unsigned a2, unsigned a3,
                                         unsigned b0, unsigned b1) {
  asm volatile(
      "mma.sync.aligned.m16n8k16.row.col.f32.f16.f16.f32 "
      "{%0,%1,%2,%3},{%4,%5,%6,%7},{%8,%9},{%0,%1,%2,%3};\n"
      : "+f"(c[0]), "+f"(c[1]), "+f"(c[2]), "+f"(c[3])
      : "r"(a0), "r"(a1), "r"(a2), "r"(a3), "r"(b0), "r"(b1));
}
__device__ __forceinline__ float sigm(float x) {
  float t, r;
  asm("ex2.approx.f32 %0, %1;" : "=f"(t) : "f"(-1.4426950408889634f * x));
  asm("rcp.approx.f32 %0, %1;" : "=f"(r) : "f"(1.0f + t));
  return r;
}
__device__ __forceinline__ float tanh_(float x) {
  x = fminf(fmaxf(x, -15.f), 15.f);
  float t, r;
  asm("ex2.approx.f32 %0, %1;" : "=f"(t) : "f"(-2.8853900817779268f * x));
  asm("rcp.approx.f32 %0, %1;" : "=f"(r) : "f"(1.0f + t));
  return (1.0f - t) * r;
}
__device__ __forceinline__ void groupbar(unsigned* ctr) {
  __syncthreads();
  if (threadIdx.x == 0) {
    asm volatile("red.release.gpu.global.add.u32 [%0], 1;" :: "l"(ctr) : "memory");
    unsigned v;
    do {
      asm volatile("ld.acquire.gpu.global.u32 %0, [%1];" : "=r"(v) : "l"(ctr) : "memory");
    } while (v < 32u);
  }
  __syncthreads();
}

// ---------- prep kernels ----------
__global__ void prep_zero() {
  unsigned i = blockIdx.x * 256u + threadIdx.x;
  if (i < 4096u) g_bar[i] = 0u;
}

// pack B-frags; adjacent kt pairs contiguous for LDS.128:
// slice idx (halfs) = (((g*2+nt)*16 + (kt>>1))*32 + lane)*8 + (kt&1)*4
__global__ void prep_pack(const float* __restrict__ whh1,
                          const float* __restrict__ wih2,
                          const float* __restrict__ whh2) {
  unsigned t = blockIdx.x * 256u + threadIdx.x;
  if (t >= 589824u) return;
  unsigned lane = t & 31u, kt = (t >> 5) & 31u, nt = (t >> 10) & 1u;
  unsigned g = (t >> 11) % 3u, hs = (t / 6144u) & 31u, gm = t / 196608u;
  const float* W = (gm == 0) ? whh1 : (gm == 1 ? wih2 : whh2);
  int j = (int)(g * 512u + hs * 16u + nt * 8u + (lane >> 2));
  int k = (int)(kt * 16u + (lane & 3u) * 2u);
  const float* wr = W + (size_t)j * 512;
  __half* dst = g_wpack[gm] + (size_t)hs * 24576u +
                ((((g * 2u + nt) * 16u + (kt >> 1)) * 32u + lane) * 8u +
                 (kt & 1u) * 4u);
  *(__half2*)(dst)     = __floats2half2_rn(wr[k], wr[k + 1]);
  *(__half2*)(dst + 2) = __floats2half2_rn(wr[k + 8], wr[k + 9]);
}

__global__ void prep_yctr(const float* __restrict__ y,
                          const float* __restrict__ wih1,
                          const float* __restrict__ bih1) {
  __shared__ float ys[127];
  int b = blockIdx.x;
  for (int c = threadIdx.x; c < 127; c += blockDim.x) ys[c] = y[b * 127 + c];
  __syncthreads();
  for (int j = threadIdx.x; j < 1536; j += blockDim.x) {
    const float* wr = wih1 + (size_t)j * 128 + 1;
    float s = bih1[j];
#pragma unroll 4
    for (int c = 0; c < 127; c++) s += ys[c] * wr[c];
    g_yctr[(size_t)b * 1536 + j] = s;
  }
}

// ---------- GEMM slice, warp-decoupled: C[3][2][4] = A(16x512) @ W(48x512)^T --
// Each warp stages ONLY its own 16 A-rows; no __syncthreads inside.
__device__ __forceinline__ void gemm_slice(const __half* __restrict__ Ag,
                                           const unsigned* __restrict__ wsmu,
                                           unsigned wst, int w, int lane,
                                           float (&C)[3][2][4]) {
#pragma unroll
  for (int g = 0; g < 3; g++)
#pragma unroll
    for (int nt = 0; nt < 2; nt++)
#pragma unroll
      for (int e = 0; e < 4; e++) C[g][nt][e] = 0.f;

  const int i0 = lane * 4;
  const int r0 = i0 >> 3, sg0 = i0 & 7;  // rows r0..r0 (4 idx = same row pair)
  // stage chunk ch into buffer buf (16 rows x 64 cols, pitch 144B)
  auto stg = [&](int ch, int buf) {
    unsigned db = wst + (unsigned)(buf * 2304);
    const __half* s = Ag + ch * 64;
#pragma unroll
    for (int i = 0; i < 4; i++) {
      int idx = i0 + i, rr = idx >> 3, seg = idx & 7;
      cp16(db + (unsigned)(rr * 144 + seg * 16),
           s + (w * 16 + rr) * 512 + seg * 8);
    }
    cpcommit();
  };
  stg(0, 0);
  const unsigned arow = wst + (unsigned)((lane & 15) * 144 + (lane >> 4) * 16);

  for (int ch = 0; ch < 8; ch++) {
    if (ch < 7) { stg(ch + 1, (ch + 1) & 1); cpwait<1>(); }
    else cpwait<0>();
    __syncwarp();
    unsigned ab = arow + (unsigned)((ch & 1) * 2304);
#pragma unroll
    for (int jp = 0; jp < 2; jp++) {
      uint4 bv[6];
#pragma unroll
      for (int q = 0; q < 6; q++)
        bv[q] = *reinterpret_cast<const uint4*>(
            wsmu + (((q * 16 + ch * 2 + jp) * 32 + lane) << 2));
#pragma unroll
      for (int j2 = 0; j2 < 2; j2++) {
        unsigned a0, a1, a2, a3;
        ldsm4(a0, a1, a2, a3, ab + (jp * 2 + j2) * 32);
#pragma unroll
        for (int q = 0; q < 6; q++)
          mma16816(C[q >> 1][q & 1], a0, a1, a2, a3,
                   j2 ? bv[q].z : bv[q].x, j2 ? bv[q].w : bv[q].y);
      }
    }
  }
}

// ---------- main persistent kernel ----------
__global__ void __launch_bounds__(256, 1)
gen_main(const float* __restrict__ z1, const float* __restrict__ y,
         const float* __restrict__ x, const float* __restrict__ hid1,
         const float* __restrict__ wih1, const float* __restrict__ bhh1g,
         const float* __restrict__ bih2g, const float* __restrict__ bhh2g,
         const float* __restrict__ wfc, const float* __restrict__ bfcp,
         float* __restrict__ dout) {
  extern __shared__ unsigned char smem[];
  __half* wsm = (__half*)smem;                        // 147456 B
  const unsigned stage0 = su32(smem + 147456);        // 8 x 4608 B
  float* yctr = (float*)(smem + 184320);              // 24576 B
  float* osm  = (float*)(smem + 208896);              // 512 B
  const unsigned* wsmu = (const unsigned*)wsm;

  const int cta = blockIdx.x;
  const int bt = cta >> 5, hs = cta & 31;
  const int tid = threadIdx.x;
  const int w = tid >> 5, lane = tid & 31;
  const unsigned wst = stage0 + (unsigned)(w * 4608);

  // weight slices -> SMEM
  {
    unsigned dbase = su32(wsm);
    for (int i = tid; i < 9216; i += 256) {
      int gm = i / 3072, q = i - gm * 3072;
      cp16(dbase + (unsigned)((gm * 24576 + q * 8) * 2),
           g_wpack[gm] + (size_t)hs * 24576 + q * 8);
    }
    cpcommit();
  }
  // ycontrib slice -> SMEM: [g][brow][hcol]
  for (int m = tid; m < 3 * 128 * 16; m += 256) {
    int g = m >> 11, rr = m & 2047, b = rr >> 4, hh = rr & 15;
    yctr[m] = g_yctr[(size_t)(bt * 128 + b) * THsz + g * 512 + hs * 16 + hh];
  }

  const int blo = w * 16 + (lane >> 2);
  const int h0 = (lane & 3) * 2;
  float bhh1[3][4], wc0[3][4], brz2[2][4], bin2[4], bhn2[4], wfcv[4];
#pragma unroll
  for (int g = 0; g < 3; g++)
#pragma unroll
    for (int i = 0; i < 4; i++) {
      int hl = (i >> 1) * 8 + h0 + (i & 1);
      int j = g * 512 + hs * 16 + hl;
      bhh1[g][i] = bhh1g[j];
      wc0[g][i] = wih1[(size_t)j * 128];
      if (g < 2) brz2[g][i] = bih2g[j] + bhh2g[j];
      else { bin2[i] = bih2g[j]; bhn2[i] = bhh2g[j]; }
    }
#pragma unroll
  for (int i = 0; i < 4; i++)
    wfcv[i] = wfc[hs * 16 + (i >> 1) * 8 + h0 + (i & 1)];
  const float bfc = bfcp[0];

  // init fp32 states + fp16 copies into buffer 0
  float s0f[2][4], s1f[2][4];
#pragma unroll
  for (int bh = 0; bh < 2; bh++) {
    int gb = bt * 128 + blo + bh * 8;
#pragma unroll
    for (int i = 0; i < 4; i++) {
      int gh = hs * 16 + (i >> 1) * 8 + h0 + (i & 1);
      s0f[bh][i] = (gh < 385) ? z1[(size_t)gb * 385 + gh]
                              : y[(size_t)gb * 127 + (gh - 385)];
      s1f[bh][i] = hid1[(size_t)gb * 512 + gh];
    }
#pragma unroll
    for (int nt = 0; nt < 2; nt++) {
      int gh = hs * 16 + nt * 8 + h0;
      *(__half2*)&g_s0h[0][(size_t)gb * 512 + gh] =
          __floats2half2_rn(s0f[bh][nt * 2], s0f[bh][nt * 2 + 1]);
      *(__half2*)&g_s1h[0][(size_t)gb * 512 + gh] =
          __floats2half2_rn(s1f[bh][nt * 2], s1f[bh][nt * 2 + 1]);
    }
  }
  if (tid < 128) osm[tid] = x[bt * 128 + tid];
  cpwait<0>();
  __syncthreads();

  unsigned* barp = &g_bar[bt * 1024];
  groupbar(barp + 512);  // init states visible group-wide

  float Cg1[3][2][4], Cg2[3][2][4];

  for (int t = 0; t < 256; t++) {
    const int pb = t & 1, nb = pb ^ 1;
    const __half* s0p = g_s0h[pb] + (size_t)bt * 65536;
    const __half* s1p = g_s1h[pb] + (size_t)bt * 65536;

    // phase 1: gh1 = s0 @ whh1^T (slice 0), gh2 = s1 @ whh2^T (slice 2)
    gemm_slice(s0p, wsmu, wst, w, lane, Cg1);
    gemm_slice(s1p, wsmu + 24576, wst, w, lane, Cg2);

    __syncthreads();  // osm from previous step's head now visible

    // cell-1 elementwise -> s0', write fp16 buf nb
    {
      float ob[2] = {osm[blo], osm[blo + 8]};
#pragma unroll
      for (int bh = 0; bh < 2; bh++) {
        int brow = blo + bh * 8;
#pragma unroll
        for (int i = 0; i < 4; i++) {
          int nt = i >> 1, e = bh * 2 + (i & 1);
          int yi = brow * 16 + nt * 8 + h0 + (i & 1);
          float gr = yctr[yi]        + ob[bh] * wc0[0][i] + Cg1[0][nt][e] + bhh1[0][i];
          float gz = yctr[2048 + yi] + ob[bh] * wc0[1][i] + Cg1[1][nt][e] + bhh1[1][i];
          float gn = yctr[4096 + yi] + ob[bh] * wc0[2][i];
          float r = sigm(gr), z = sigm(gz);
          float n = tanh_(gn + r * (Cg1[2][nt][e] + bhh1[2][i]));
          s0f[bh][i] = (1.f - z) * n + z * s0f[bh][i];
        }
        int gb = bt * 128 + brow;
#pragma unroll
        for (int nt = 0; nt < 2; nt++)
          *(__half2*)&g_s0h[nb][(size_t)gb * 512 + hs * 16 + nt * 8 + h0] =
              __floats2half2_rn(s0f[bh][nt * 2], s0f[bh][nt * 2 + 1]);
      }
    }
    groupbar(barp + t * 2);

    // phase 2: gi2 = s0' @ wih2^T (slice 1)
    gemm_slice(g_s0h[nb] + (size_t)bt * 65536, wsmu + 12288, wst, w, lane, Cg1);

    // cell-2 elementwise -> s1', fc partials
    {
#pragma unroll
      for (int bh = 0; bh < 2; bh++) {
        float p = 0.f;
#pragma unroll
        for (int i = 0; i < 4; i++) {
          int nt = i >> 1, e = bh * 2 + (i & 1);
          float r = sigm(Cg1[0][nt][e] + Cg2[0][nt][e] + brz2[0][i]);
          float z = sigm(Cg1[1][nt][e] + Cg2[1][nt][e] + brz2[1][i]);
          float n = tanh_(Cg1[2][nt][e] + bin2[i] + r * (Cg2[2][nt][e] + bhn2[i]));
          s1f[bh][i] = (1.f - z) * n + z * s1f[bh][i];
          p += s1f[bh][i] * wfcv[i];
        }
        int gb = bt * 128 + blo + bh * 8;
#pragma unroll
        for (int nt = 0; nt < 2; nt++)
          *(__half2*)&g_s1h[nb][(size_t)gb * 512 + hs * 16 + nt * 8 + h0] =
              __floats2half2_rn(s1f[bh][nt * 2], s1f[bh][nt * 2 + 1]);
        p += __shfl_xor_sync(0xffffffffu, p, 1);
        p += __shfl_xor_sync(0xffffffffu, p, 2);
        if ((lane & 3) == 0) __stcg(&g_fcpart[(size_t)gb * 32 + hs], p);
      }
    }
    groupbar(barp + t * 2 + 1);

    // output head: o = relu(bfc + sum partials); overlaps next step's gemms
    if (tid < 128) {
      const float* fp = &g_fcpart[(size_t)(bt * 128 + tid) * 32];
      float s = bfc;
#pragma unroll 8
      for (int k = 0; k < 32; k++) s += __ldcg(fp + k);
      float o = fmaxf(s, 0.f);
      osm[tid] = o;
      if (hs == 0) dout[(size_t)(bt * 128 + tid) * 256 + t] = o;
    }
  }
}

}  // namespace

extern "C" void kernel_launch(void* const* d_in, const int* in_sizes, int n_in,
                              void* d_out, int out_size) {
  const float* z1   = (const float*)d_in[0];
  const float* y    = (const float*)d_in[1];
  const float* x    = (const float*)d_in[2];
  const float* h1   = (const float*)d_in[3];
  const float* wih1 = (const float*)d_in[4];
  const float* whh1 = (const float*)d_in[5];
  const float* bih1 = (const float*)d_in[6];
  const float* bhh1 = (const float*)d_in[7];
  const float* wih2 = (const float*)d_in[8];
  const float* whh2 = (const float*)d_in[9];
  const float* bih2 = (const float*)d_in[10];
  const float* bhh2 = (const float*)d_in[11];
  const float* wfc  = (const float*)d_in[12];
  const float* bfc  = (const float*)d_in[13];

  cudaFuncSetAttribute(gen_main, cudaFuncAttributeMaxDynamicSharedMemorySize,
                       SMEM_BYTES);

  prep_zero<<<16, 256>>>();
  prep_pack<<<2304, 256>>>(whh1, wih2, whh2);
  prep_yctr<<<512, 256>>>(y, wih1, bih1);
  gen_main<<<128, 256, SMEM_BYTES>>>(z1, y, x, h1, wih1, bhh1, bih2, bhh2,
                                     wfc, bfc, (float*)d_out);
}

// round 11
// speedup vs baseline: 1.1504x; 1.1504x over previous
#include <cuda_runtime.h>
#include <cuda_fp16.h>

#define SMEM_BYTES 221696

namespace {

// ---------- device scratch ----------
__device__ __half   g_wpack[3][786432];
__device__ float    g_yctr[512 * 1536];
__device__ __half   g_s0h[2][512 * 512];
__device__ __half   g_s1h[2][512 * 512];
__device__ float    g_fcpart[512 * 64];
__device__ unsigned g_bar[4096];

// ---------- helpers ----------
__device__ __forceinline__ unsigned su32(const void* p) {
  return (unsigned)__cvta_generic_to_shared(p);
}
__device__ __forceinline__ void cp16(unsigned d, const void* s) {
  asm volatile("cp.async.cg.shared.global [%0], [%1], 16;\n" :: "r"(d), "l"(s));
}
__device__ __forceinline__ void cpcommit() { asm volatile("cp.async.commit_group;\n"); }
template <int N> __device__ __forceinline__ void cpwait() {
  asm volatile("cp.async.wait_group %0;\n" :: "n"(N));
}
__device__ __forceinline__ void ldsm4(unsigned& r0, unsigned& r1, unsigned& r2,
                                      unsigned& r3, unsigned a) {
  asm volatile("ldmatrix.sync.aligned.m8n8.x4.shared.b16 {%0,%1,%2,%3}, [%4];\n"
               : "=r"(r0), "=r"(r1), "=r"(r2), "=r"(r3) : "r"(a));
}
__device__ __forceinline__ void mma16816(float* c, unsigned a0, unsigned a1,
                                         unsigned a2, unsigned a3,
                                         unsigned b0, unsigned b1) {
  asm volatile(
      "mma.sync.aligned.m16n8k16.row.col.f32.f16.f16.f32 "
      "{%0,%1,%2,%3},{%4,%5,%6,%7},{%8,%9},{%0,%1,%2,%3};\n"
      : "+f"(c[0]), "+f"(c[1]), "+f"(c[2]), "+f"(c[3])
      : "r"(a0), "r"(a1), "r"(a2), "r"(a3), "r"(b0), "r"(b1));
}
__device__ __forceinline__ float sigm(float x) {
  float t, r;
  asm("ex2.approx.f32 %0, %1;" : "=f"(t) : "f"(-1.4426950408889634f * x));
  asm("rcp.approx.f32 %0, %1;" : "=f"(r) : "f"(1.0f + t));
  return r;
}
__device__ __forceinline__ float tanh_(float x) {
  x = fminf(fmaxf(x, -15.f), 15.f);
  float t, r;
  asm("ex2.approx.f32 %0, %1;" : "=f"(t) : "f"(-2.8853900817779268f * x));
  asm("rcp.approx.f32 %0, %1;" : "=f"(r) : "f"(1.0f + t));
  return (1.0f - t) * r;
}
__device__ __forceinline__ void groupbar(unsigned* ctr) {
  __syncthreads();
  if (threadIdx.x == 0) {
    asm volatile("red.release.gpu.global.add.u32 [%0], 1;" :: "l"(ctr) : "memory");
    unsigned v;
    do {
      asm volatile("ld.acquire.gpu.global.u32 %0, [%1];" : "=r"(v) : "l"(ctr) : "memory");
    } while (v < 32u);
  }
  __syncthreads();
}

// ---------- prep kernels ----------
__global__ void prep_zero() {
  unsigned i = blockIdx.x * 256u + threadIdx.x;
  if (i < 4096u) g_bar[i] = 0u;
}

// pack B-frags, adjacent kt pairs contiguous for LDS.128 (validated in R10):
// halfs idx = (((g*2+nt)*16 + (kt>>1))*32 + lane)*8 + (kt&1)*4
__global__ void prep_pack(const float* __restrict__ whh1,
                          const float* __restrict__ wih2,
                          const float* __restrict__ whh2) {
  unsigned t = blockIdx.x * 256u + threadIdx.x;
  if (t >= 589824u) return;
  unsigned lane = t & 31u, kt = (t >> 5) & 31u, nt = (t >> 10) & 1u;
  unsigned g = (t >> 11) % 3u, hs = (t / 6144u) & 31u, gm = t / 196608u;
  const float* W = (gm == 0) ? whh1 : (gm == 1 ? wih2 : whh2);
  int j = (int)(g * 512u + hs * 16u + nt * 8u + (lane >> 2));
  int k = (int)(kt * 16u + (lane & 3u) * 2u);
  const float* wr = W + (size_t)j * 512;
  __half* dst = g_wpack[gm] + (size_t)hs * 24576u +
                ((((g * 2u + nt) * 16u + (kt >> 1)) * 32u + lane) * 8u +
                 (kt & 1u) * 4u);
  *(__half2*)(dst)     = __floats2half2_rn(wr[k], wr[k + 1]);
  *(__half2*)(dst + 2) = __floats2half2_rn(wr[k + 8], wr[k + 9]);
}

__global__ void prep_yctr(const float* __restrict__ y,
                          const float* __restrict__ wih1,
                          const float* __restrict__ bih1) {
  __shared__ float ys[127];
  int b = blockIdx.x;
  for (int c = threadIdx.x; c < 127; c += blockDim.x) ys[c] = y[b * 127 + c];
  __syncthreads();
  for (int j = threadIdx.x; j < 1536; j += blockDim.x) {
    const float* wr = wih1 + (size_t)j * 128 + 1;
    float s = bih1[j];
#pragma unroll 4
    for (int c = 0; c < 127; c++) s += ys[c] * wr[c];
    g_yctr[(size_t)b * 1536 + j] = s;
  }
}

// ---------- main persistent kernel: 512 threads, 16 warps ----------
// warp w: m-tile mt=w>>1 (rows mt*16..+15), n-half nt=w&1 (h-cols nt*8..+7)
__global__ void __launch_bounds__(512, 1)
gen_main(const float* __restrict__ z1, const float* __restrict__ y,
         const float* __restrict__ x, const float* __restrict__ hid1,
         const float* __restrict__ wih1, const float* __restrict__ bhh1g,
         const float* __restrict__ bih2g, const float* __restrict__ bhh2g,
         const float* __restrict__ wfc, const float* __restrict__ bfcp,
         float* __restrict__ dout) {
  extern __shared__ unsigned char smem[];
  __half* wsm = (__half*)smem;                   // 147456 B (3 slices)
  const unsigned stage0 = su32(smem + 147456);   // 2 slots x 2 bufs x 18432 B
  float* osm = (float*)(smem + 221184);          // 128 f32
  const unsigned* wsmu = (const unsigned*)wsm;

  const int cta = blockIdx.x, bt = cta >> 5, hs = cta & 31;
  const int tid = threadIdx.x, w = tid >> 5, lane = tid & 31;
  const int mt = w >> 1, nt = w & 1;

  // weight slices -> SMEM
  {
    unsigned dbase = su32(wsm);
    for (int i = tid; i < 9216; i += 512) {
      int gm = i / 3072, q = i - gm * 3072;
      cp16(dbase + (unsigned)((gm * 24576 + q * 8) * 2),
           g_wpack[gm] + (size_t)hs * 24576 + q * 8);
    }
    cpcommit();
  }

  const int h0 = (lane & 3) * 2;
  const int jj0 = hs * 16 + nt * 8 + h0;          // global h of col 0
  const int brow = mt * 16 + (lane >> 2);         // local batch row (second = +8)

  // per-thread constants
  float bhh1[3][2], wc0[3][2], brz2[2][2], bin2[2], bhn2[2], wfcv[2];
#pragma unroll
  for (int g = 0; g < 3; g++)
#pragma unroll
    for (int i = 0; i < 2; i++) {
      int j = g * 512 + jj0 + i;
      bhh1[g][i] = bhh1g[j];
      wc0[g][i] = wih1[(size_t)j * 128];
      if (g < 2) brz2[g][i] = bih2g[j] + bhh2g[j];
      else { bin2[i] = bih2g[j]; bhn2[i] = bhh2g[j]; }
    }
  wfcv[0] = wfc[jj0]; wfcv[1] = wfc[jj0 + 1];
  const float bfc = bfcp[0];

  // loop-invariant ycontrib (y constant across scan): 12 regs
  float yc[3][2][2];
  // states
  float s0f[2][2], s1f[2][2];
#pragma unroll
  for (int bh = 0; bh < 2; bh++) {
    int gb = bt * 128 + brow + bh * 8;
    const float* yb = g_yctr + (size_t)gb * 1536 + jj0;
#pragma unroll
    for (int g = 0; g < 3; g++) {
      yc[g][bh][0] = yb[g * 512];
      yc[g][bh][1] = yb[g * 512 + 1];
    }
#pragma unroll
    for (int i = 0; i < 2; i++) {
      int gh = jj0 + i;
      s0f[bh][i] = (gh < 385) ? z1[(size_t)gb * 385 + gh]
                              : y[(size_t)gb * 127 + (gh - 385)];
      s1f[bh][i] = hid1[(size_t)gb * 512 + gh];
    }
    *(__half2*)&g_s0h[0][(size_t)gb * 512 + jj0] =
        __floats2half2_rn(s0f[bh][0], s0f[bh][1]);
    *(__half2*)&g_s1h[0][(size_t)gb * 512 + jj0] =
        __floats2half2_rn(s1f[bh][0], s1f[bh][1]);
  }
  if (tid < 128) osm[tid] = x[bt * 128 + tid];
  cpwait<0>();
  __syncthreads();

  unsigned* barp = &g_bar[bt * 1024];
  groupbar(barp + 512);

  const unsigned arow =
      (unsigned)(((mt * 16 + (lane & 15)) * 72 + (lane >> 4) * 8) * 2);
  float Cg1[3][4], Cg2[3][4];

  for (int t = 0; t < 256; t++) {
    const int pb = t & 1, nb = pb ^ 1;
    const __half* s0p = g_s0h[pb] + (size_t)bt * 65536;
    const __half* s1p = g_s1h[pb] + (size_t)bt * 65536;

    // ---- phase 1: gh1 (slice0, A=s0) and gh2 (slice2, A=s1), fused ----
#pragma unroll
    for (int g = 0; g < 3; g++)
#pragma unroll
      for (int e = 0; e < 4; e++) { Cg1[g][e] = 0.f; Cg2[g][e] = 0.f; }
    {
      auto stg2 = [&](int ch) {
        unsigned db = stage0 + (unsigned)((ch & 1) * 18432);
#pragma unroll
        for (int i = 0; i < 2; i++) {
          int idx = tid * 2 + i, rr = idx >> 3, seg = idx & 7;
          unsigned off = (unsigned)(rr * 144 + seg * 16);
          cp16(db + off, s0p + rr * 512 + ch * 64 + seg * 8);
          cp16(db + 36864 + off, s1p + rr * 512 + ch * 64 + seg * 8);
        }
        cpcommit();
      };
      stg2(0);
      for (int ch = 0; ch < 8; ch++) {
        if (ch < 7) { stg2(ch + 1); cpwait<1>(); } else cpwait<0>();
        __syncthreads();
        unsigned abA = stage0 + (unsigned)((ch & 1) * 18432) + arow;
        unsigned abB = abA + 36864;
#pragma unroll
        for (int jp = 0; jp < 2; jp++) {
          uint4 bA[3], bB[3];
#pragma unroll
          for (int g = 0; g < 3; g++) {
            unsigned widx =
                (unsigned)((((g * 2 + nt) * 16 + ch * 2 + jp) * 32 + lane) << 2);
            bA[g] = *reinterpret_cast<const uint4*>(wsmu + widx);
            bB[g] = *reinterpret_cast<const uint4*>(wsmu + 24576 + widx);
          }
#pragma unroll
          for (int j2 = 0; j2 < 2; j2++) {
            unsigned a0, a1, a2, a3;
            ldsm4(a0, a1, a2, a3, abA + (jp * 2 + j2) * 32);
#pragma unroll
            for (int g = 0; g < 3; g++)
              mma16816(Cg1[g], a0, a1, a2, a3,
                       j2 ? bA[g].z : bA[g].x, j2 ? bA[g].w : bA[g].y);
            ldsm4(a0, a1, a2, a3, abB + (jp * 2 + j2) * 32);
#pragma unroll
            for (int g = 0; g < 3; g++)
              mma16816(Cg2[g], a0, a1, a2, a3,
                       j2 ? bB[g].z : bB[g].x, j2 ? bB[g].w : bB[g].y);
          }
        }
        __syncthreads();
      }
    }

    // ---- cell-1 elementwise -> s0' ----
    {
      float ob[2] = {osm[brow], osm[brow + 8]};
#pragma unroll
      for (int bh = 0; bh < 2; bh++) {
#pragma unroll
        for (int i = 0; i < 2; i++) {
          int e = bh * 2 + i;
          float gr = yc[0][bh][i] + ob[bh] * wc0[0][i] + Cg1[0][e] + bhh1[0][i];
          float gz = yc[1][bh][i] + ob[bh] * wc0[1][i] + Cg1[1][e] + bhh1[1][i];
          float gn = yc[2][bh][i] + ob[bh] * wc0[2][i];
          float r = sigm(gr), z = sigm(gz);
          float n = tanh_(gn + r * (Cg1[2][e] + bhh1[2][i]));
          s0f[bh][i] = (1.f - z) * n + z * s0f[bh][i];
        }
        int gb = bt * 128 + brow + bh * 8;
        *(__half2*)&g_s0h[nb][(size_t)gb * 512 + jj0] =
            __floats2half2_rn(s0f[bh][0], s0f[bh][1]);
      }
    }
    groupbar(barp + t * 2);

    // ---- phase 2: gi2 (slice1, A=s0') ----
#pragma unroll
    for (int g = 0; g < 3; g++)
#pragma unroll
      for (int e = 0; e < 4; e++) Cg1[g][e] = 0.f;
    {
      const __half* s0n = g_s0h[nb] + (size_t)bt * 65536;
      auto stg1 = [&](int ch) {
        unsigned db = stage0 + (unsigned)((ch & 1) * 18432);
#pragma unroll
        for (int i = 0; i < 2; i++) {
          int idx = tid * 2 + i, rr = idx >> 3, seg = idx & 7;
          cp16(db + (unsigned)(rr * 144 + seg * 16),
               s0n + rr * 512 + ch * 64 + seg * 8);
        }
        cpcommit();
      };
      stg1(0);
      for (int ch = 0; ch < 8; ch++) {
        if (ch < 7) { stg1(ch + 1); cpwait<1>(); } else cpwait<0>();
        __syncthreads();
        unsigned abA = stage0 + (unsigned)((ch & 1) * 18432) + arow;
#pragma unroll
        for (int jp = 0; jp < 2; jp++) {
          uint4 bA[3];
#pragma unroll
          for (int g = 0; g < 3; g++) {
            unsigned widx =
                (unsigned)((((g * 2 + nt) * 16 + ch * 2 + jp) * 32 + lane) << 2);
            bA[g] = *reinterpret_cast<const uint4*>(wsmu + 12288 + widx);
          }
#pragma unroll
          for (int j2 = 0; j2 < 2; j2++) {
            unsigned a0, a1, a2, a3;
            ldsm4(a0, a1, a2, a3, abA + (jp * 2 + j2) * 32);
#pragma unroll
            for (int g = 0; g < 3; g++)
              mma16816(Cg1[g], a0, a1, a2, a3,
                       j2 ? bA[g].z : bA[g].x, j2 ? bA[g].w : bA[g].y);
          }
        }
        __syncthreads();
      }
    }

    // ---- cell-2 elementwise -> s1', fc partials ----
    {
#pragma unroll
      for (int bh = 0; bh < 2; bh++) {
#pragma unroll
        for (int i = 0; i < 2; i++) {
          int e = bh * 2 + i;
          float r = sigm(Cg1[0][e] + Cg2[0][e] + brz2[0][i]);
          float z = sigm(Cg1[1][e] + Cg2[1][e] + brz2[1][i]);
          float n = tanh_(Cg1[2][e] + bin2[i] + r * (Cg2[2][e] + bhn2[i]));
          s1f[bh][i] = (1.f - z) * n + z * s1f[bh][i];
        }
        int gb = bt * 128 + brow + bh * 8;
        *(__half2*)&g_s1h[nb][(size_t)gb * 512 + jj0] =
            __floats2half2_rn(s1f[bh][0], s1f[bh][1]);
        float p = s1f[bh][0] * wfcv[0] + s1f[bh][1] * wfcv[1];
        p += __shfl_xor_sync(0xffffffffu, p, 1);
        p += __shfl_xor_sync(0xffffffffu, p, 2);
        if ((lane & 3) == 0)
          __stcg(&g_fcpart[(size_t)gb * 64 + hs * 2 + nt], p);
      }
    }
    groupbar(barp + t * 2 + 1);

    // ---- output head (overlaps next step's gemms) ----
    if (tid < 128) {
      const float* fp = &g_fcpart[(size_t)(bt * 128 + tid) * 64];
      float s = bfc;
#pragma unroll 16
      for (int k = 0; k < 64; k++) s += __ldcg(fp + k);
      float o = fmaxf(s, 0.f);
      osm[tid] = o;
      if (hs == 0) dout[(size_t)(bt * 128 + tid) * 256 + t] = o;
    }
  }
}

}  // namespace

extern "C" void kernel_launch(void* const* d_in, const int* in_sizes, int n_in,
                              void* d_out, int out_size) {
  const float* z1   = (const float*)d_in[0];
  const float* y    = (const float*)d_in[1];
  const float* x    = (const float*)d_in[2];
  const float* h1   = (const float*)d_in[3];
  const float* wih1 = (const float*)d_in[4];
  const float* whh1 = (const float*)d_in[5];
  const float* bih1 = (const float*)d_in[6];
  const float* bhh1 = (const float*)d_in[7];
  const float* wih2 = (const float*)d_in[8];
  const float* whh2 = (const float*)d_in[9];
  const float* bih2 = (const float*)d_in[10];
  const float* bhh2 = (const float*)d_in[11];
  const float* wfc  = (const float*)d_in[12];
  const float* bfc  = (const float*)d_in[13];

  cudaFuncSetAttribute(gen_main, cudaFuncAttributeMaxDynamicSharedMemorySize,
                       SMEM_BYTES);

  prep_zero<<<16, 256>>>();
  prep_pack<<<2304, 256>>>(whh1, wih2, whh2);
  prep_yctr<<<512, 256>>>(y, wih1, bih1);
  gen_main<<<128, 512, SMEM_BYTES>>>(z1, y, x, h1, wih1, bhh1, bih2, bhh2,
                                     wfc, bfc, (float*)d_out);
}

// round 12
// speedup vs baseline: 1.4716x; 1.2792x over previous
#include <cuda_runtime.h>
#include <cuda_fp16.h>

#define SMEM_BYTES 221696  // 147456 wt + 73728 stage + 512 osm

namespace {

// ---------- device scratch ----------
__device__ __half   g_wpack[3][786432];
__device__ float    g_yctr[512 * 1536];
__device__ __half   g_s0h[2][512 * 512];
__device__ __half   g_s1h[2][512 * 512];
__device__ float    g_fcpart[512 * 32];
__device__ unsigned g_bar[4096];

// ---------- helpers ----------
__device__ __forceinline__ unsigned su32(const void* p) {
  return (unsigned)__cvta_generic_to_shared(p);
}
__device__ __forceinline__ void cp16(unsigned d, const void* s) {
  asm volatile("cp.async.cg.shared.global [%0], [%1], 16;\n" :: "r"(d), "l"(s));
}
__device__ __forceinline__ void cpcommit() { asm volatile("cp.async.commit_group;\n"); }
template <int N> __device__ __forceinline__ void cpwait() {
  asm volatile("cp.async.wait_group %0;\n" :: "n"(N));
}
__device__ __forceinline__ void ldsm4(unsigned& r0, unsigned& r1, unsigned& r2,
                                      unsigned& r3, unsigned a) {
  asm volatile("ldmatrix.sync.aligned.m8n8.x4.shared.b16 {%0,%1,%2,%3}, [%4];\n"
               : "=r"(r0), "=r"(r1), "=r"(r2), "=r"(r3) : "r"(a));
}
__device__ __forceinline__ void mma16816(float* c, unsigned a0, unsigned a1,
                                         unsigned a2, unsigned a3,
                                         unsigned b0, unsigned b1) {
  asm volatile(
      "mma.sync.aligned.m16n8k16.row.col.f32.f16.f16.f32 "
      "{%0,%1,%2,%3},{%4,%5,%6,%7},{%8,%9},{%0,%1,%2,%3};\n"
      : "+f"(c[0]), "+f"(c[1]), "+f"(c[2]), "+f"(c[3])
      : "r"(a0), "r"(a1), "r"(a2), "r"(a3), "r"(b0), "r"(b1));
}
__device__ __forceinline__ float sigm(float x) {
  float t, r;
  asm("ex2.approx.f32 %0, %1;" : "=f"(t) : "f"(-1.4426950408889634f * x));
  asm("rcp.approx.f32 %0, %1;" : "=f"(r) : "f"(1.0f + t));
  return r;
}
__device__ __forceinline__ float tanh_(float x) {
  x = fminf(fmaxf(x, -15.f), 15.f);
  float t, r;
  asm("ex2.approx.f32 %0, %1;" : "=f"(t) : "f"(-2.8853900817779268f * x));
  asm("rcp.approx.f32 %0, %1;" : "=f"(r) : "f"(1.0f + t));
  return (1.0f - t) * r;
}
__device__ __forceinline__ void bar_arrive(unsigned* ctr) {
  __syncthreads();
  if (threadIdx.x == 0)
    asm volatile("red.release.gpu.global.add.u32 [%0], 1;" :: "l"(ctr) : "memory");
}
__device__ __forceinline__ void bar_wait(unsigned* ctr) {
  if (threadIdx.x == 0) {
    unsigned v;
    do {
      asm volatile("ld.acquire.gpu.global.u32 %0, [%1];" : "=r"(v) : "l"(ctr) : "memory");
    } while (v < 32u);
  }
  __syncthreads();
}

// ---------- prep kernels ----------
__global__ void prep_zero() {
  unsigned i = blockIdx.x * 256u + threadIdx.x;
  if (i < 4096u) g_bar[i] = 0u;
}

// B-frag pack, adjacent kt pairs contiguous for LDS.128 (validated R10/R11):
// halfs idx = (((g*2+nt)*16 + (kt>>1))*32 + lane)*8 + (kt&1)*4
__global__ void prep_pack(const float* __restrict__ whh1,
                          const float* __restrict__ wih2,
                          const float* __restrict__ whh2) {
  unsigned t = blockIdx.x * 256u + threadIdx.x;
  if (t >= 589824u) return;
  unsigned lane = t & 31u, kt = (t >> 5) & 31u, nt = (t >> 10) & 1u;
  unsigned g = (t >> 11) % 3u, hs = (t / 6144u) & 31u, gm = t / 196608u;
  const float* W = (gm == 0) ? whh1 : (gm == 1 ? wih2 : whh2);
  int j = (int)(g * 512u + hs * 16u + nt * 8u + (lane >> 2));
  int k = (int)(kt * 16u + (lane & 3u) * 2u);
  const float* wr = W + (size_t)j * 512;
  __half* dst = g_wpack[gm] + (size_t)hs * 24576u +
                ((((g * 2u + nt) * 16u + (kt >> 1)) * 32u + lane) * 8u +
                 (kt & 1u) * 4u);
  *(__half2*)(dst)     = __floats2half2_rn(wr[k], wr[k + 1]);
  *(__half2*)(dst + 2) = __floats2half2_rn(wr[k + 8], wr[k + 9]);
}

__global__ void prep_yctr(const float* __restrict__ y,
                          const float* __restrict__ wih1,
                          const float* __restrict__ bih1) {
  __shared__ float ys[127];
  int b = blockIdx.x;
  for (int c = threadIdx.x; c < 127; c += blockDim.x) ys[c] = y[b * 127 + c];
  __syncthreads();
  for (int j = threadIdx.x; j < 1536; j += blockDim.x) {
    const float* wr = wih1 + (size_t)j * 128 + 1;
    float s = bih1[j];
#pragma unroll 4
    for (int c = 0; c < 127; c++) s += ys[c] * wr[c];
    g_yctr[(size_t)b * 1536 + j] = s;
  }
}

// ---------- GEMM slice, warp-private 4-deep, no __syncthreads ----------
// warp w computes rows w*16..+15 x 48 cols; stages ONLY its own rows.
__device__ __forceinline__ void gemm_slice(const __half* __restrict__ Ag,
                                           const unsigned* __restrict__ wsmu,
                                           unsigned wst, int w, int lane,
                                           float (&C)[3][2][4]) {
#pragma unroll
  for (int g = 0; g < 3; g++)
#pragma unroll
    for (int nt = 0; nt < 2; nt++)
#pragma unroll
      for (int e = 0; e < 4; e++) C[g][nt][e] = 0.f;

  const int i0 = lane * 4;
  auto stg = [&](int ch) {
    if (ch < 8) {
      unsigned db = wst + (unsigned)((ch & 3) * 2304);
      const __half* s = Ag + ch * 64;
#pragma unroll
      for (int i = 0; i < 4; i++) {
        int idx = i0 + i, rr = idx >> 3, seg = idx & 7;
        cp16(db + (unsigned)(rr * 144 + seg * 16),
             s + (w * 16 + rr) * 512 + seg * 8);
      }
    }
    cpcommit();
  };
  stg(0); stg(1); stg(2);
  const unsigned arow = wst + (unsigned)((lane & 15) * 144 + (lane >> 4) * 16);

  for (int ch = 0; ch < 8; ch++) {
    stg(ch + 3);       // commits every iter (empty beyond 7)
    cpwait<3>();       // own group ch complete (warp-private buffer)
    __syncwarp();
    unsigned ab = arow + (unsigned)((ch & 3) * 2304);
#pragma unroll
    for (int jp = 0; jp < 2; jp++) {
      uint4 bv[6];
#pragma unroll
      for (int q = 0; q < 6; q++)
        bv[q] = *reinterpret_cast<const uint4*>(
            wsmu + (((q * 16 + ch * 2 + jp) * 32 + lane) << 2));
#pragma unroll
      for (int j2 = 0; j2 < 2; j2++) {
        unsigned a0, a1, a2, a3;
        ldsm4(a0, a1, a2, a3, ab + (jp * 2 + j2) * 32);
#pragma unroll
        for (int q = 0; q < 6; q++)
          mma16816(C[q >> 1][q & 1], a0, a1, a2, a3,
                   j2 ? bv[q].z : bv[q].x, j2 ? bv[q].w : bv[q].y);
      }
    }
  }
}

// ---------- main persistent kernel ----------
__global__ void __launch_bounds__(256, 1)
gen_main(const float* __restrict__ z1, const float* __restrict__ y,
         const float* __restrict__ x, const float* __restrict__ hid1,
         const float* __restrict__ wih1, const float* __restrict__ bhh1g,
         const float* __restrict__ bih2g, const float* __restrict__ bhh2g,
         const float* __restrict__ wfc, const float* __restrict__ bfcp,
         float* __restrict__ dout) {
  extern __shared__ unsigned char smem[];
  __half* wsm = (__half*)smem;                   // 147456 B
  const unsigned stage0 = su32(smem + 147456);   // 8 warps x 4 bufs x 2304 B
  float* osm = (float*)(smem + 221184);          // 128 f32
  const unsigned* wsmu = (const unsigned*)wsm;

  const int cta = blockIdx.x, bt = cta >> 5, hs = cta & 31;
  const int tid = threadIdx.x, w = tid >> 5, lane = tid & 31;
  const unsigned wst = stage0 + (unsigned)(w * 9216);

  // weight slices -> SMEM
  {
    unsigned dbase = su32(wsm);
    for (int i = tid; i < 9216; i += 256) {
      int gm = i / 3072, q = i - gm * 3072;
      cp16(dbase + (unsigned)((gm * 24576 + q * 8) * 2),
           g_wpack[gm] + (size_t)hs * 24576 + q * 8);
    }
    cpcommit();
  }

  const int blo = w * 16 + (lane >> 2);
  const int h0 = (lane & 3) * 2;
  float bhh1[3][4], wc0[3][4], brz2[2][4], bin2[4], bhn2[4], wfcv[4];
#pragma unroll
  for (int g = 0; g < 3; g++)
#pragma unroll
    for (int i = 0; i < 4; i++) {
      int hl = (i >> 1) * 8 + h0 + (i & 1);
      int j = g * 512 + hs * 16 + hl;
      bhh1[g][i] = bhh1g[j];
      wc0[g][i] = wih1[(size_t)j * 128];
      if (g < 2) brz2[g][i] = bih2g[j] + bhh2g[j];
      else { bin2[i] = bih2g[j]; bhn2[i] = bhh2g[j]; }
    }
#pragma unroll
  for (int i = 0; i < 4; i++)
    wfcv[i] = wfc[hs * 16 + (i >> 1) * 8 + h0 + (i & 1)];
  const float bfc = bfcp[0];

  // loop-invariant ycontrib in regs + state init
  float yc[3][2][4], s0f[2][4], s1f[2][4];
#pragma unroll
  for (int bh = 0; bh < 2; bh++) {
    int gb = bt * 128 + blo + bh * 8;
#pragma unroll
    for (int i = 0; i < 4; i++) {
      int hl = (i >> 1) * 8 + h0 + (i & 1);
      int gh = hs * 16 + hl;
#pragma unroll
      for (int g = 0; g < 3; g++)
        yc[g][bh][i] = g_yctr[(size_t)gb * 1536 + g * 512 + gh];
      s0f[bh][i] = (gh < 385) ? z1[(size_t)gb * 385 + gh]
                              : y[(size_t)gb * 127 + (gh - 385)];
      s1f[bh][i] = hid1[(size_t)gb * 512 + gh];
    }
#pragma unroll
    for (int nt = 0; nt < 2; nt++) {
      int gh = hs * 16 + nt * 8 + h0;
      *(__half2*)&g_s0h[0][(size_t)gb * 512 + gh] =
          __floats2half2_rn(s0f[bh][nt * 2], s0f[bh][nt * 2 + 1]);
      *(__half2*)&g_s1h[0][(size_t)gb * 512 + gh] =
          __floats2half2_rn(s1f[bh][nt * 2], s1f[bh][nt * 2 + 1]);
    }
  }
  if (tid < 128) osm[tid] = x[bt * 128 + tid];
  cpwait<0>();
  __syncthreads();

  unsigned* barp = &g_bar[bt * 1024];
  bar_arrive(barp + 512);
  bar_wait(barp + 512);

  float Cg1[3][2][4], Cg2[3][2][4], Ci[3][2][4];

  // pre-loop: gh1 for t=0
  gemm_slice(g_s0h[0] + (size_t)bt * 65536, wsmu, wst, w, lane, Cg1);

  for (int t = 0; t < 256; t++) {
    const int pb = t & 1, nb = pb ^ 1;

    // head for step t-1 (hidden behind prior gh1; waits bar2[t-1])
    if (t > 0) {
      bar_wait(barp + (t - 1) * 2 + 1);
      if (tid < 128) {
        const float* fp = &g_fcpart[(size_t)(bt * 128 + tid) * 32];
        float s = bfc;
#pragma unroll 8
        for (int k = 0; k < 32; k++) s += __ldcg(fp + k);
        float o = fmaxf(s, 0.f);
        osm[tid] = o;
        if (hs == 0) dout[(size_t)(bt * 128 + tid) * 256 + (t - 1)] = o;
      }
    }
    __syncthreads();  // osm visible

    // ---- cell-1: Cg1 + o + yc -> s0' ----
    {
      float ob[2] = {osm[blo], osm[blo + 8]};
#pragma unroll
      for (int bh = 0; bh < 2; bh++) {
#pragma unroll
        for (int i = 0; i < 4; i++) {
          int nt = i >> 1, e = bh * 2 + (i & 1);
          float gr = yc[0][bh][i] + ob[bh] * wc0[0][i] + Cg1[0][nt][e] + bhh1[0][i];
          float gz = yc[1][bh][i] + ob[bh] * wc0[1][i] + Cg1[1][nt][e] + bhh1[1][i];
          float gn = yc[2][bh][i] + ob[bh] * wc0[2][i];
          float r = sigm(gr), z = sigm(gz);
          float n = tanh_(gn + r * (Cg1[2][nt][e] + bhh1[2][i]));
          s0f[bh][i] = (1.f - z) * n + z * s0f[bh][i];
        }
        int gb = bt * 128 + blo + bh * 8;
#pragma unroll
        for (int nt = 0; nt < 2; nt++)
          *(__half2*)&g_s0h[nb][(size_t)gb * 512 + hs * 16 + nt * 8 + h0] =
              __floats2half2_rn(s0f[bh][nt * 2], s0f[bh][nt * 2 + 1]);
      }
    }
    bar_arrive(barp + t * 2);  // s0' published

    // ---- gh2 = s1 @ whh2^T (independent of s0'; hides bar1 latency) ----
    gemm_slice(g_s1h[pb] + (size_t)bt * 65536, wsmu + 24576, wst, w, lane, Cg2);

    bar_wait(barp + t * 2);  // all s0' visible

    // ---- gi2 = s0' @ wih2^T ----
    gemm_slice(g_s0h[nb] + (size_t)bt * 65536, wsmu + 12288, wst, w, lane, Ci);

    // ---- cell-2 -> s1', fc partials ----
    {
#pragma unroll
      for (int bh = 0; bh < 2; bh++) {
        float p = 0.f;
#pragma unroll
        for (int i = 0; i < 4; i++) {
          int nt = i >> 1, e = bh * 2 + (i & 1);
          float r = sigm(Ci[0][nt][e] + Cg2[0][nt][e] + brz2[0][i]);
          float z = sigm(Ci[1][nt][e] + Cg2[1][nt][e] + brz2[1][i]);
          float n = tanh_(Ci[2][nt][e] + bin2[i] + r * (Cg2[2][nt][e] + bhn2[i]));
          s1f[bh][i] = (1.f - z) * n + z * s1f[bh][i];
          p += s1f[bh][i] * wfcv[i];
        }
        int gb = bt * 128 + blo + bh * 8;
#pragma unroll
        for (int nt = 0; nt < 2; nt++)
          *(__half2*)&g_s1h[nb][(size_t)gb * 512 + hs * 16 + nt * 8 + h0] =
              __floats2half2_rn(s1f[bh][nt * 2], s1f[bh][nt * 2 + 1]);
        p += __shfl_xor_sync(0xffffffffu, p, 1);
        p += __shfl_xor_sync(0xffffffffu, p, 2);
        if ((lane & 3) == 0) __stcg(&g_fcpart[(size_t)gb * 32 + hs], p);
      }
    }
    bar_arrive(barp + t * 2 + 1);  // s1' + fcpart published

    // ---- gh1 for t+1 (s0' already synced at bar1; hides bar2 latency) ----
    gemm_slice(g_s0h[nb] + (size_t)bt * 65536, wsmu, wst, w, lane, Cg1);
  }

  // final head (o[255])
  bar_wait(barp + 255 * 2 + 1);
  if (tid < 128 && hs == 0) {
    const float* fp = &g_fcpart[(size_t)(bt * 128 + tid) * 32];
    float s = bfc;
#pragma unroll 8
    for (int k = 0; k < 32; k++) s += __ldcg(fp + k);
    dout[(size_t)(bt * 128 + tid) * 256 + 255] = fmaxf(s, 0.f);
  }
}

}  // namespace

extern "C" void kernel_launch(void* const* d_in, const int* in_sizes, int n_in,
                              void* d_out, int out_size) {
  const float* z1   = (const float*)d_in[0];
  const float* y    = (const float*)d_in[1];
  const float* x    = (const float*)d_in[2];
  const float* h1   = (const float*)d_in[3];
  const float* wih1 = (const float*)d_in[4];
  const float* whh1 = (const float*)d_in[5];
  const float* bih1 = (const float*)d_in[6];
  const float* bhh1 = (const float*)d_in[7];
  const float* wih2 = (const float*)d_in[8];
  const float* whh2 = (const float*)d_in[9];
  const float* bih2 = (const float*)d_in[10];
  const float* bhh2 = (const float*)d_in[11];
  const float* wfc  = (const float*)d_in[12];
  const float* bfc  = (const float*)d_in[13];

  cudaFuncSetAttribute(gen_main, cudaFuncAttributeMaxDynamicSharedMemorySize,
                       SMEM_BYTES);

  prep_zero<<<16, 256>>>();
  prep_pack<<<2304, 256>>>(whh1, wih2, whh2);
  prep_yctr<<<512, 256>>>(y, wih1, bih1);
  gen_main<<<128, 256, SMEM_BYTES>>>(z1, y, x, h1, wih1, bhh1, bih2, bhh2,
                                     wfc, bfc, (float*)d_out);
}

// round 13
// speedup vs baseline: 1.6267x; 1.1054x over previous
#include <cuda_runtime.h>
#include <cuda_fp16.h>

#define SMEM_BYTES 222400  // 147456 wt + 73728 stage + 512 osm + 704 btile

namespace {

// ---------- device scratch ----------
__device__ __half   g_wpack[3][786432];
__device__ float    g_yctr[512 * 1536];
__device__ __half   g_s0h[2][512 * 512];
__device__ __half   g_s1h[2][512 * 512];
__device__ float    g_fcpart[512 * 32];
__device__ unsigned g_bar[4096];

// ---------- helpers ----------
__device__ __forceinline__ unsigned su32(const void* p) {
  return (unsigned)__cvta_generic_to_shared(p);
}
__device__ __forceinline__ void cp16(unsigned d, const void* s) {
  asm volatile("cp.async.cg.shared.global [%0], [%1], 16;\n" :: "r"(d), "l"(s));
}
__device__ __forceinline__ void cpcommit() { asm volatile("cp.async.commit_group;\n"); }
template <int N> __device__ __forceinline__ void cpwait() {
  asm volatile("cp.async.wait_group %0;\n" :: "n"(N));
}
__device__ __forceinline__ void ldsm4(unsigned& r0, unsigned& r1, unsigned& r2,
                                      unsigned& r3, unsigned a) {
  asm volatile("ldmatrix.sync.aligned.m8n8.x4.shared.b16 {%0,%1,%2,%3}, [%4];\n"
               : "=r"(r0), "=r"(r1), "=r"(r2), "=r"(r3) : "r"(a));
}
__device__ __forceinline__ void mma16816(float* c, unsigned a0, unsigned a1,
                                         unsigned a2, unsigned a3,
                                         unsigned b0, unsigned b1) {
  asm volatile(
      "mma.sync.aligned.m16n8k16.row.col.f32.f16.f16.f32 "
      "{%0,%1,%2,%3},{%4,%5,%6,%7},{%8,%9},{%0,%1,%2,%3};\n"
      : "+f"(c[0]), "+f"(c[1]), "+f"(c[2]), "+f"(c[3])
      : "r"(a0), "r"(a1), "r"(a2), "r"(a3), "r"(b0), "r"(b1));
}
__device__ __forceinline__ float sigm(float x) {
  float t, r;
  asm("ex2.approx.f32 %0, %1;" : "=f"(t) : "f"(-1.4426950408889634f * x));
  asm("rcp.approx.f32 %0, %1;" : "=f"(r) : "f"(1.0f + t));
  return r;
}
__device__ __forceinline__ float tanh_(float x) {
  x = fminf(fmaxf(x, -15.f), 15.f);
  float t, r;
  asm("ex2.approx.f32 %0, %1;" : "=f"(t) : "f"(-2.8853900817779268f * x));
  asm("rcp.approx.f32 %0, %1;" : "=f"(r) : "f"(1.0f + t));
  return (1.0f - t) * r;
}
__device__ __forceinline__ void bar_arrive(unsigned* ctr) {
  __syncthreads();
  if (threadIdx.x == 0)
    asm volatile("red.release.gpu.global.add.u32 [%0], 1;" :: "l"(ctr) : "memory");
}
__device__ __forceinline__ void bar_wait(unsigned* ctr) {
  if (threadIdx.x == 0) {
    unsigned v;
    do {
      asm volatile("ld.acquire.gpu.global.u32 %0, [%1];" : "=r"(v) : "l"(ctr) : "memory");
    } while (v < 32u);
  }
  __syncthreads();
}

// ---------- prep kernels (identical to R12) ----------
__global__ void prep_zero() {
  unsigned i = blockIdx.x * 256u + threadIdx.x;
  if (i < 4096u) g_bar[i] = 0u;
}

__global__ void prep_pack(const float* __restrict__ whh1,
                          const float* __restrict__ wih2,
                          const float* __restrict__ whh2) {
  unsigned t = blockIdx.x * 256u + threadIdx.x;
  if (t >= 589824u) return;
  unsigned lane = t & 31u, kt = (t >> 5) & 31u, nt = (t >> 10) & 1u;
  unsigned g = (t >> 11) % 3u, hs = (t / 6144u) & 31u, gm = t / 196608u;
  const float* W = (gm == 0) ? whh1 : (gm == 1 ? wih2 : whh2);
  int j = (int)(g * 512u + hs * 16u + nt * 8u + (lane >> 2));
  int k = (int)(kt * 16u + (lane & 3u) * 2u);
  const float* wr = W + (size_t)j * 512;
  __half* dst = g_wpack[gm] + (size_t)hs * 24576u +
                ((((g * 2u + nt) * 16u + (kt >> 1)) * 32u + lane) * 8u +
                 (kt & 1u) * 4u);
  *(__half2*)(dst)     = __floats2half2_rn(wr[k], wr[k + 1]);
  *(__half2*)(dst + 2) = __floats2half2_rn(wr[k + 8], wr[k + 9]);
}

__global__ void prep_yctr(const float* __restrict__ y,
                          const float* __restrict__ wih1,
                          const float* __restrict__ bih1) {
  __shared__ float ys[127];
  int b = blockIdx.x;
  for (int c = threadIdx.x; c < 127; c += blockDim.x) ys[c] = y[b * 127 + c];
  __syncthreads();
  for (int j = threadIdx.x; j < 1536; j += blockDim.x) {
    const float* wr = wih1 + (size_t)j * 128 + 1;
    float s = bih1[j];
#pragma unroll 4
    for (int c = 0; c < 127; c++) s += ys[c] * wr[c];
    g_yctr[(size_t)b * 1536 + j] = s;
  }
}

// ---------- single GEMM slice (R12, validated) ----------
__device__ __forceinline__ void gemm_slice(const __half* __restrict__ Ag,
                                           const unsigned* __restrict__ wsmu,
                                           unsigned wst, int w, int lane,
                                           float (&C)[3][2][4]) {
#pragma unroll
  for (int g = 0; g < 3; g++)
#pragma unroll
    for (int nt = 0; nt < 2; nt++)
#pragma unroll
      for (int e = 0; e < 4; e++) C[g][nt][e] = 0.f;
  const int i0 = lane * 4;
  auto stg = [&](int ch) {
    if (ch < 8) {
      unsigned db = wst + (unsigned)((ch & 3) * 2304);
      const __half* s = Ag + ch * 64;
#pragma unroll
      for (int i = 0; i < 4; i++) {
        int idx = i0 + i, rr = idx >> 3, seg = idx & 7;
        cp16(db + (unsigned)(rr * 144 + seg * 16),
             s + (w * 16 + rr) * 512 + seg * 8);
      }
    }
    cpcommit();
  };
  stg(0); stg(1); stg(2);
  const unsigned arow = wst + (unsigned)((lane & 15) * 144 + (lane >> 4) * 16);
  for (int ch = 0; ch < 8; ch++) {
    stg(ch + 3);
    cpwait<3>();
    __syncwarp();
    unsigned ab = arow + (unsigned)((ch & 3) * 2304);
#pragma unroll
    for (int jp = 0; jp < 2; jp++) {
      uint4 bv[6];
#pragma unroll
      for (int q = 0; q < 6; q++)
        bv[q] = *reinterpret_cast<const uint4*>(
            wsmu + (((q * 16 + ch * 2 + jp) * 32 + lane) << 2));
#pragma unroll
      for (int j2 = 0; j2 < 2; j2++) {
        unsigned a0, a1, a2, a3;
        ldsm4(a0, a1, a2, a3, ab + (jp * 2 + j2) * 32);
#pragma unroll
        for (int q = 0; q < 6; q++)
          mma16816(C[q >> 1][q & 1], a0, a1, a2, a3,
                   j2 ? bv[q].z : bv[q].x, j2 ? bv[q].w : bv[q].y);
      }
    }
  }
}

// ---------- dual GEMM: one A stream, two B slices, two C outputs ----------
__device__ __forceinline__ void gemm_dual(const __half* __restrict__ Ag,
                                          const unsigned* __restrict__ wsmP,
                                          const unsigned* __restrict__ wsmQ,
                                          unsigned wst, int w, int lane,
                                          float (&CP)[3][2][4],
                                          float (&CQ)[3][2][4]) {
#pragma unroll
  for (int g = 0; g < 3; g++)
#pragma unroll
    for (int nt = 0; nt < 2; nt++)
#pragma unroll
      for (int e = 0; e < 4; e++) { CP[g][nt][e] = 0.f; CQ[g][nt][e] = 0.f; }
  const int i0 = lane * 4;
  auto stg = [&](int ch) {
    if (ch < 8) {
      unsigned db = wst + (unsigned)((ch & 3) * 2304);
      const __half* s = Ag + ch * 64;
#pragma unroll
      for (int i = 0; i < 4; i++) {
        int idx = i0 + i, rr = idx >> 3, seg = idx & 7;
        cp16(db + (unsigned)(rr * 144 + seg * 16),
             s + (w * 16 + rr) * 512 + seg * 8);
      }
    }
    cpcommit();
  };
  stg(0); stg(1); stg(2);
  const unsigned arow = wst + (unsigned)((lane & 15) * 144 + (lane >> 4) * 16);
  for (int ch = 0; ch < 8; ch++) {
    stg(ch + 3);
    cpwait<3>();
    __syncwarp();
    unsigned ab = arow + (unsigned)((ch & 3) * 2304);
#pragma unroll
    for (int jp = 0; jp < 2; jp++) {
      unsigned widx[6];
#pragma unroll
      for (int q = 0; q < 6; q++)
        widx[q] = ((q * 16 + ch * 2 + jp) * 32 + lane) << 2;
      uint4 bP[6];
#pragma unroll
      for (int q = 0; q < 6; q++)
        bP[q] = *reinterpret_cast<const uint4*>(wsmP + widx[q]);
#pragma unroll
      for (int j2 = 0; j2 < 2; j2++) {
        unsigned a0, a1, a2, a3;
        ldsm4(a0, a1, a2, a3, ab + (jp * 2 + j2) * 32);
#pragma unroll
        for (int q = 0; q < 6; q++)
          mma16816(CP[q >> 1][q & 1], a0, a1, a2, a3,
                   j2 ? bP[q].z : bP[q].x, j2 ? bP[q].w : bP[q].y);
        // second slice reuses the SAME A fragments
        uint4 bQ;
#pragma unroll
        for (int q = 0; q < 6; q++) {
          bQ = *reinterpret_cast<const uint4*>(wsmQ + widx[q]);
          mma16816(CQ[q >> 1][q & 1], a0, a1, a2, a3,
                   j2 ? bQ.z : bQ.x, j2 ? bQ.w : bQ.y);
        }
      }
    }
  }
}

// ---------- main persistent kernel ----------
__global__ void __launch_bounds__(256, 1)
gen_main(const float* __restrict__ z1, const float* __restrict__ y,
         const float* __restrict__ x, const float* __restrict__ hid1,
         const float* __restrict__ wih1, const float* __restrict__ bhh1g,
         const float* __restrict__ bih2g, const float* __restrict__ bhh2g,
         const float* __restrict__ wfc, const float* __restrict__ bfcp,
         float* __restrict__ dout) {
  extern __shared__ unsigned char smem[];
  __half* wsm = (__half*)smem;                   // 147456 B
  const unsigned stage0 = su32(smem + 147456);   // 8 warps x 4 bufs x 2304 B
  float* osm = (float*)(smem + 221184);          // 128 f32
  float* btile = (float*)(smem + 221696);        // 176 f32
  const unsigned* wsmu = (const unsigned*)wsm;

  const int cta = blockIdx.x, bt = cta >> 5, hs = cta & 31;
  const int tid = threadIdx.x, w = tid >> 5, lane = tid & 31;
  const unsigned wst = stage0 + (unsigned)(w * 9216);

  // weight slices -> SMEM
  {
    unsigned dbase = su32(wsm);
    for (int i = tid; i < 9216; i += 256) {
      int gm = i / 3072, q = i - gm * 3072;
      cp16(dbase + (unsigned)((gm * 24576 + q * 8) * 2),
           g_wpack[gm] + (size_t)hs * 24576 + q * 8);
    }
    cpcommit();
  }
  // bias tile -> SMEM
  if (tid < 16) {
    int j = tid, jj = hs * 16 + j;
    btile[j]       = bhh1g[jj];
    btile[16 + j]  = bhh1g[512 + jj];
    btile[32 + j]  = bhh1g[1024 + jj];
    btile[48 + j]  = wih1[(size_t)jj * 128];
    btile[64 + j]  = wih1[(size_t)(512 + jj) * 128];
    btile[80 + j]  = wih1[(size_t)(1024 + jj) * 128];
    btile[96 + j]  = bih2g[jj] + bhh2g[jj];
    btile[112 + j] = bih2g[512 + jj] + bhh2g[512 + jj];
    btile[128 + j] = bih2g[1024 + jj];
    btile[144 + j] = bhh2g[1024 + jj];
    btile[160 + j] = wfc[jj];
  }

  const int blo = w * 16 + (lane >> 2);
  const int h0 = (lane & 3) * 2;
  const float bfc = bfcp[0];

  // loop-invariant ycontrib in regs + state init
  float yc[3][2][4], s0f[2][4], s1f[2][4];
#pragma unroll
  for (int bh = 0; bh < 2; bh++) {
    int gb = bt * 128 + blo + bh * 8;
#pragma unroll
    for (int i = 0; i < 4; i++) {
      int hl = (i >> 1) * 8 + h0 + (i & 1);
      int gh = hs * 16 + hl;
#pragma unroll
      for (int g = 0; g < 3; g++)
        yc[g][bh][i] = g_yctr[(size_t)gb * 1536 + g * 512 + gh];
      s0f[bh][i] = (gh < 385) ? z1[(size_t)gb * 385 + gh]
                              : y[(size_t)gb * 127 + (gh - 385)];
      s1f[bh][i] = hid1[(size_t)gb * 512 + gh];
    }
#pragma unroll
    for (int nt = 0; nt < 2; nt++) {
      int gh = hs * 16 + nt * 8 + h0;
      *(__half2*)&g_s0h[0][(size_t)gb * 512 + gh] =
          __floats2half2_rn(s0f[bh][nt * 2], s0f[bh][nt * 2 + 1]);
      *(__half2*)&g_s1h[0][(size_t)gb * 512 + gh] =
          __floats2half2_rn(s1f[bh][nt * 2], s1f[bh][nt * 2 + 1]);
    }
  }
  if (tid < 128) osm[tid] = x[bt * 128 + tid];
  cpwait<0>();
  __syncthreads();

  unsigned* barp = &g_bar[bt * 1024];
  bar_arrive(barp + 512);
  bar_wait(barp + 512);

  float Cg1[3][2][4], Cg2[3][2][4], Ci[3][2][4];

  // pre-loop: gh1 for t=0
  gemm_slice(g_s0h[0] + (size_t)bt * 65536, wsmu, wst, w, lane, Cg1);

  for (int t = 0; t < 256; t++) {
    const int pb = t & 1, nb = pb ^ 1;

    // head for t-1 (after bar2[t-1])
    if (t > 0) {
      bar_wait(barp + (t - 1) * 2 + 1);
      if (tid < 128) {
        const float* fp = &g_fcpart[(size_t)(bt * 128 + tid) * 32];
        float s = bfc;
#pragma unroll 8
        for (int k = 0; k < 32; k++) s += __ldcg(fp + k);
        float o = fmaxf(s, 0.f);
        osm[tid] = o;
        if (hs == 0) dout[(size_t)(bt * 128 + tid) * 256 + (t - 1)] = o;
      }
    }
    __syncthreads();

    // ---- cell-1 -> s0' ----
    {
      float ob[2] = {osm[blo], osm[blo + 8]};
#pragma unroll
      for (int bh = 0; bh < 2; bh++) {
#pragma unroll
        for (int i = 0; i < 4; i++) {
          int nt = i >> 1, e = bh * 2 + (i & 1);
          int hl = nt * 8 + h0 + (i & 1);
          float gr = yc[0][bh][i] + ob[bh] * btile[48 + hl] + Cg1[0][nt][e] + btile[hl];
          float gz = yc[1][bh][i] + ob[bh] * btile[64 + hl] + Cg1[1][nt][e] + btile[16 + hl];
          float gn = yc[2][bh][i] + ob[bh] * btile[80 + hl];
          float r = sigm(gr), z = sigm(gz);
          float n = tanh_(gn + r * (Cg1[2][nt][e] + btile[32 + hl]));
          s0f[bh][i] = (1.f - z) * n + z * s0f[bh][i];
        }
        int gb = bt * 128 + blo + bh * 8;
#pragma unroll
        for (int nt = 0; nt < 2; nt++)
          *(__half2*)&g_s0h[nb][(size_t)gb * 512 + hs * 16 + nt * 8 + h0] =
              __floats2half2_rn(s0f[bh][nt * 2], s0f[bh][nt * 2 + 1]);
      }
    }
    bar_arrive(barp + t * 2);  // s0' published

    // ---- gh2 = s1 @ whh2^T (hides bar1) ----
    gemm_slice(g_s1h[pb] + (size_t)bt * 65536, wsmu + 24576, wst, w, lane, Cg2);

    bar_wait(barp + t * 2);  // all s0' visible

    // ---- fused: gi2 (slice1) + gh1 for t+1 (slice0), one A pass ----
    gemm_dual(g_s0h[nb] + (size_t)bt * 65536, wsmu + 12288, wsmu, wst, w, lane,
              Ci, Cg1);

    // ---- cell-2 -> s1', fc partials ----
    {
#pragma unroll
      for (int bh = 0; bh < 2; bh++) {
        float p = 0.f;
#pragma unroll
        for (int i = 0; i < 4; i++) {
          int nt = i >> 1, e = bh * 2 + (i & 1);
          int hl = nt * 8 + h0 + (i & 1);
          float r = sigm(Ci[0][nt][e] + Cg2[0][nt][e] + btile[96 + hl]);
          float z = sigm(Ci[1][nt][e] + Cg2[1][nt][e] + btile[112 + hl]);
          float n = tanh_(Ci[2][nt][e] + btile[128 + hl] +
                          r * (Cg2[2][nt][e] + btile[144 + hl]));
          s1f[bh][i] = (1.f - z) * n + z * s1f[bh][i];
          p += s1f[bh][i] * btile[160 + hl];
        }
        int gb = bt * 128 + blo + bh * 8;
#pragma unroll
        for (int nt = 0; nt < 2; nt++)
          *(__half2*)&g_s1h[nb][(size_t)gb * 512 + hs * 16 + nt * 8 + h0] =
              __floats2half2_rn(s1f[bh][nt * 2], s1f[bh][nt * 2 + 1]);
        p += __shfl_xor_sync(0xffffffffu, p, 1);
        p += __shfl_xor_sync(0xffffffffu, p, 2);
        if ((lane & 3) == 0) __stcg(&g_fcpart[(size_t)gb * 32 + hs], p);
      }
    }
    bar_arrive(barp + t * 2 + 1);  // s1' + fcpart published
  }

  // final head (o[255])
  bar_wait(barp + 255 * 2 + 1);
  if (tid < 128 && hs == 0) {
    const float* fp = &g_fcpart[(size_t)(bt * 128 + tid) * 32];
    float s = bfc;
#pragma unroll 8
    for (int k = 0; k < 32; k++) s += __ldcg(fp + k);
    dout[(size_t)(bt * 128 + tid) * 256 + 255] = fmaxf(s, 0.f);
  }
}

}  // namespace

extern "C" void kernel_launch(void* const* d_in, const int* in_sizes, int n_in,
                              void* d_out, int out_size) {
  const float* z1   = (const float*)d_in[0];
  const float* y    = (const float*)d_in[1];
  const float* x    = (const float*)d_in[2];
  const float* h1   = (const float*)d_in[3];
  const float* wih1 = (const float*)d_in[4];
  const float* whh1 = (const float*)d_in[5];
  const float* bih1 = (const float*)d_in[6];
  const float* bhh1 = (const float*)d_in[7];
  const float* wih2 = (const float*)d_in[8];
  const float* whh2 = (const float*)d_in[9];
  const float* bih2 = (const float*)d_in[10];
  const float* bhh2 = (const float*)d_in[11];
  const float* wfc  = (const float*)d_in[12];
  const float* bfc  = (const float*)d_in[13];

  cudaFuncSetAttribute(gen_main, cudaFuncAttributeMaxDynamicSharedMemorySize,
                       SMEM_BYTES);

  prep_zero<<<16, 256>>>();
  prep_pack<<<2304, 256>>>(whh1, wih2, whh2);
  prep_yctr<<<512, 256>>>(y, wih1, bih1);
  gen_main<<<128, 256, SMEM_BYTES>>>(z1, y, x, h1, wih1, bhh1, bih2, bhh2,
                                     wfc, bfc, (float*)d_out);
}

// round 14
// speedup vs baseline: 1.6323x; 1.0034x over previous
#include <cuda_runtime.h>
#include <cuda_fp16.h>

#define SMEM_BYTES 222400  // 147456 wt + 73728 stage + 512 osm + 704 btile

namespace {

// ---------- device scratch ----------
__device__ __half   g_wpack[3][786432];
__device__ float    g_yctr[512 * 1536];
__device__ __half   g_s0h[2][512 * 512];
__device__ __half   g_s1h[2][512 * 512];
__device__ float    g_fcpart[512 * 32];
__device__ unsigned g_bar[4096];

// ---------- helpers ----------
__device__ __forceinline__ unsigned su32(const void* p) {
  return (unsigned)__cvta_generic_to_shared(p);
}
__device__ __forceinline__ void cp16(unsigned d, const void* s) {
  asm volatile("cp.async.cg.shared.global [%0], [%1], 16;\n" :: "r"(d), "l"(s));
}
__device__ __forceinline__ void cpcommit() { asm volatile("cp.async.commit_group;\n"); }
template <int N> __device__ __forceinline__ void cpwait() {
  asm volatile("cp.async.wait_group %0;\n" :: "n"(N));
}
__device__ __forceinline__ void ldsm4(unsigned& r0, unsigned& r1, unsigned& r2,
                                      unsigned& r3, unsigned a) {
  asm volatile("ldmatrix.sync.aligned.m8n8.x4.shared.b16 {%0,%1,%2,%3}, [%4];\n"
               : "=r"(r0), "=r"(r1), "=r"(r2), "=r"(r3) : "r"(a));
}
__device__ __forceinline__ void mma16816(float* c, unsigned a0, unsigned a1,
                                         unsigned a2, unsigned a3,
                                         unsigned b0, unsigned b1) {
  asm volatile(
      "mma.sync.aligned.m16n8k16.row.col.f32.f16.f16.f32 "
      "{%0,%1,%2,%3},{%4,%5,%6,%7},{%8,%9},{%0,%1,%2,%3};\n"
      : "+f"(c[0]), "+f"(c[1]), "+f"(c[2]), "+f"(c[3])
      : "r"(a0), "r"(a1), "r"(a2), "r"(a3), "r"(b0), "r"(b1));
}
__device__ __forceinline__ float sigm(float x) {
  float t, r;
  asm("ex2.approx.f32 %0, %1;" : "=f"(t) : "f"(-1.4426950408889634f * x));
  asm("rcp.approx.f32 %0, %1;" : "=f"(r) : "f"(1.0f + t));
  return r;
}
__device__ __forceinline__ float tanh_(float x) {
  x = fminf(fmaxf(x, -15.f), 15.f);
  float t, r;
  asm("ex2.approx.f32 %0, %1;" : "=f"(t) : "f"(-2.8853900817779268f * x));
  asm("rcp.approx.f32 %0, %1;" : "=f"(r) : "f"(1.0f + t));
  return (1.0f - t) * r;
}
__device__ __forceinline__ void bar_arrive(unsigned* ctr) {
  __syncthreads();
  if (threadIdx.x == 0)
    asm volatile("red.release.gpu.global.add.u32 [%0], 1;" :: "l"(ctr) : "memory");
}
__device__ __forceinline__ void bar_wait(unsigned* ctr) {
  if (threadIdx.x == 0) {
    unsigned v;
    do {
      asm volatile("ld.acquire.gpu.global.u32 %0, [%1];" : "=r"(v) : "l"(ctr) : "memory");
    } while (v < 32u);
  }
  __syncthreads();
}

// ---------- prep kernels ----------
__global__ void prep_zero() {
  unsigned i = blockIdx.x * 256u + threadIdx.x;
  if (i < 4096u) g_bar[i] = 0u;
}

__global__ void prep_pack(const float* __restrict__ whh1,
                          const float* __restrict__ wih2,
                          const float* __restrict__ whh2) {
  unsigned t = blockIdx.x * 256u + threadIdx.x;
  if (t >= 589824u) return;
  unsigned lane = t & 31u, kt = (t >> 5) & 31u, nt = (t >> 10) & 1u;
  unsigned g = (t >> 11) % 3u, hs = (t / 6144u) & 31u, gm = t / 196608u;
  const float* W = (gm == 0) ? whh1 : (gm == 1 ? wih2 : whh2);
  int j = (int)(g * 512u + hs * 16u + nt * 8u + (lane >> 2));
  int k = (int)(kt * 16u + (lane & 3u) * 2u);
  const float* wr = W + (size_t)j * 512;
  __half* dst = g_wpack[gm] + (size_t)hs * 24576u +
                ((((g * 2u + nt) * 16u + (kt >> 1)) * 32u + lane) * 8u +
                 (kt & 1u) * 4u);
  *(__half2*)(dst)     = __floats2half2_rn(wr[k], wr[k + 1]);
  *(__half2*)(dst + 2) = __floats2half2_rn(wr[k + 8], wr[k + 9]);
}

__global__ void prep_yctr(const float* __restrict__ y,
                          const float* __restrict__ wih1,
                          const float* __restrict__ bih1) {
  __shared__ float ys[127];
  int b = blockIdx.x;
  for (int c = threadIdx.x; c < 127; c += blockDim.x) ys[c] = y[b * 127 + c];
  __syncthreads();
  for (int j = threadIdx.x; j < 1536; j += blockDim.x) {
    const float* wr = wih1 + (size_t)j * 128 + 1;
    float s = bih1[j];
#pragma unroll 4
    for (int c = 0; c < 127; c++) s += ys[c] * wr[c];
    g_yctr[(size_t)b * 1536 + j] = s;
  }
}

// ---------- single GEMM slice (R12/R13, validated) ----------
__device__ __forceinline__ void gemm_slice(const __half* __restrict__ Ag,
                                           const unsigned* __restrict__ wsmu,
                                           unsigned wst, int w, int lane,
                                           float (&C)[3][2][4]) {
#pragma unroll
  for (int g = 0; g < 3; g++)
#pragma unroll
    for (int nt = 0; nt < 2; nt++)
#pragma unroll
      for (int e = 0; e < 4; e++) C[g][nt][e] = 0.f;
  const int i0 = lane * 4;
  auto stg = [&](int ch) {
    if (ch < 8) {
      unsigned db = wst + (unsigned)((ch & 3) * 2304);
      const __half* s = Ag + ch * 64;
#pragma unroll
      for (int i = 0; i < 4; i++) {
        int idx = i0 + i, rr = idx >> 3, seg = idx & 7;
        cp16(db + (unsigned)(rr * 144 + seg * 16),
             s + (w * 16 + rr) * 512 + seg * 8);
      }
    }
    cpcommit();
  };
  stg(0); stg(1); stg(2);
  const unsigned arow = wst + (unsigned)((lane & 15) * 144 + (lane >> 4) * 16);
  for (int ch = 0; ch < 8; ch++) {
    stg(ch + 3);
    cpwait<3>();
    __syncwarp();
    unsigned ab = arow + (unsigned)((ch & 3) * 2304);
#pragma unroll
    for (int jp = 0; jp < 2; jp++) {
      uint4 bv[6];
#pragma unroll
      for (int q = 0; q < 6; q++)
        bv[q] = *reinterpret_cast<const uint4*>(
            wsmu + (((q * 16 + ch * 2 + jp) * 32 + lane) << 2));
#pragma unroll
      for (int j2 = 0; j2 < 2; j2++) {
        unsigned a0, a1, a2, a3;
        ldsm4(a0, a1, a2, a3, ab + (jp * 2 + j2) * 32);
#pragma unroll
        for (int q = 0; q < 6; q++)
          mma16816(C[q >> 1][q & 1], a0, a1, a2, a3,
                   j2 ? bv[q].z : bv[q].x, j2 ? bv[q].w : bv[q].y);
      }
    }
  }
}

// ---------- dual GEMM: one A stream, two B slices, single-load Q ----------
__device__ __forceinline__ void gemm_dual(const __half* __restrict__ Ag,
                                          const unsigned* __restrict__ wsmP,
                                          const unsigned* __restrict__ wsmQ,
                                          unsigned wst, int w, int lane,
                                          float (&CP)[3][2][4],
                                          float (&CQ)[3][2][4]) {
#pragma unroll
  for (int g = 0; g < 3; g++)
#pragma unroll
    for (int nt = 0; nt < 2; nt++)
#pragma unroll
      for (int e = 0; e < 4; e++) { CP[g][nt][e] = 0.f; CQ[g][nt][e] = 0.f; }
  const int i0 = lane * 4;
  auto stg = [&](int ch) {
    if (ch < 8) {
      unsigned db = wst + (unsigned)((ch & 3) * 2304);
      const __half* s = Ag + ch * 64;
#pragma unroll
      for (int i = 0; i < 4; i++) {
        int idx = i0 + i, rr = idx >> 3, seg = idx & 7;
        cp16(db + (unsigned)(rr * 144 + seg * 16),
             s + (w * 16 + rr) * 512 + seg * 8);
      }
    }
    cpcommit();
  };
  stg(0); stg(1); stg(2);
  const unsigned arow = wst + (unsigned)((lane & 15) * 144 + (lane >> 4) * 16);
  for (int ch = 0; ch < 8; ch++) {
    stg(ch + 3);
    cpwait<3>();
    __syncwarp();
    unsigned ab = arow + (unsigned)((ch & 3) * 2304);
#pragma unroll
    for (int jp = 0; jp < 2; jp++) {
      // both A k-sub-tiles for this jp (reused by P and Q)
      unsigned x0, x1, x2, x3, y0, y1, y2, y3;
      ldsm4(x0, x1, x2, x3, ab + (jp * 2 + 0) * 32);
      ldsm4(y0, y1, y2, y3, ab + (jp * 2 + 1) * 32);
      unsigned widx[6];
#pragma unroll
      for (int q = 0; q < 6; q++)
        widx[q] = ((q * 16 + ch * 2 + jp) * 32 + lane) << 2;
      uint4 bv[6];
#pragma unroll
      for (int q = 0; q < 6; q++)
        bv[q] = *reinterpret_cast<const uint4*>(wsmP + widx[q]);
#pragma unroll
      for (int q = 0; q < 6; q++) {
        mma16816(CP[q >> 1][q & 1], x0, x1, x2, x3, bv[q].x, bv[q].y);
        mma16816(CP[q >> 1][q & 1], y0, y1, y2, y3, bv[q].z, bv[q].w);
      }
#pragma unroll
      for (int q = 0; q < 6; q++)
        bv[q] = *reinterpret_cast<const uint4*>(wsmQ + widx[q]);
#pragma unroll
      for (int q = 0; q < 6; q++) {
        mma16816(CQ[q >> 1][q & 1], x0, x1, x2, x3, bv[q].x, bv[q].y);
        mma16816(CQ[q >> 1][q & 1], y0, y1, y2, y3, bv[q].z, bv[q].w);
      }
    }
  }
}

// ---------- main persistent kernel ----------
__global__ void __launch_bounds__(256, 1)
gen_main(const float* __restrict__ z1, const float* __restrict__ y,
         const float* __restrict__ x, const float* __restrict__ hid1,
         const float* __restrict__ wih1, const float* __restrict__ bhh1g,
         const float* __restrict__ bih2g, const float* __restrict__ bhh2g,
         const float* __restrict__ wfc, const float* __restrict__ bfcp,
         float* __restrict__ dout) {
  extern __shared__ unsigned char smem[];
  __half* wsm = (__half*)smem;                   // 147456 B
  const unsigned stage0 = su32(smem + 147456);   // 8 warps x 4 bufs x 2304 B
  float* osm = (float*)(smem + 221184);          // 128 f32
  float* btile = (float*)(smem + 221696);        // 176 f32
  const unsigned* wsmu = (const unsigned*)wsm;

  const int cta = blockIdx.x, bt = cta >> 5, hs = cta & 31;
  const int tid = threadIdx.x, w = tid >> 5, lane = tid & 31;
  const unsigned wst = stage0 + (unsigned)(w * 9216);

  // weight slices -> SMEM
  {
    unsigned dbase = su32(wsm);
    for (int i = tid; i < 9216; i += 256) {
      int gm = i / 3072, q = i - gm * 3072;
      cp16(dbase + (unsigned)((gm * 24576 + q * 8) * 2),
           g_wpack[gm] + (size_t)hs * 24576 + q * 8);
    }
    cpcommit();
  }
  // bias tile -> SMEM
  if (tid < 16) {
    int j = tid, jj = hs * 16 + j;
    btile[j]       = bhh1g[jj];
    btile[16 + j]  = bhh1g[512 + jj];
    btile[32 + j]  = bhh1g[1024 + jj];
    btile[48 + j]  = wih1[(size_t)jj * 128];
    btile[64 + j]  = wih1[(size_t)(512 + jj) * 128];
    btile[80 + j]  = wih1[(size_t)(1024 + jj) * 128];
    btile[96 + j]  = bih2g[jj] + bhh2g[jj];
    btile[112 + j] = bih2g[512 + jj] + bhh2g[512 + jj];
    btile[128 + j] = bih2g[1024 + jj];
    btile[144 + j] = bhh2g[1024 + jj];
    btile[160 + j] = wfc[jj];
  }

  const int blo = w * 16 + (lane >> 2);
  const int h0 = (lane & 3) * 2;
  const float bfc = bfcp[0];

  // loop-invariant ycontrib in regs + state init
  float yc[3][2][4], s0f[2][4], s1f[2][4];
#pragma unroll
  for (int bh = 0; bh < 2; bh++) {
    int gb = bt * 128 + blo + bh * 8;
#pragma unroll
    for (int i = 0; i < 4; i++) {
      int hl = (i >> 1) * 8 + h0 + (i & 1);
      int gh = hs * 16 + hl;
#pragma unroll
      for (int g = 0; g < 3; g++)
        yc[g][bh][i] = g_yctr[(size_t)gb * 1536 + g * 512 + gh];
      s0f[bh][i] = (gh < 385) ? z1[(size_t)gb * 385 + gh]
                              : y[(size_t)gb * 127 + (gh - 385)];
      s1f[bh][i] = hid1[(size_t)gb * 512 + gh];
    }
#pragma unroll
    for (int nt = 0; nt < 2; nt++) {
      int gh = hs * 16 + nt * 8 + h0;
      *(__half2*)&g_s0h[0][(size_t)gb * 512 + gh] =
          __floats2half2_rn(s0f[bh][nt * 2], s0f[bh][nt * 2 + 1]);
      *(__half2*)&g_s1h[0][(size_t)gb * 512 + gh] =
          __floats2half2_rn(s1f[bh][nt * 2], s1f[bh][nt * 2 + 1]);
    }
  }
  if (tid < 128) osm[tid] = x[bt * 128 + tid];
  cpwait<0>();
  __syncthreads();

  unsigned* barp = &g_bar[bt * 1024];
  bar_arrive(barp + 512);
  bar_wait(barp + 512);

  float Cg1[3][2][4], Cg2[3][2][4], Ci[3][2][4];

  // pre-loop: gh1 for t=0
  gemm_slice(g_s0h[0] + (size_t)bt * 65536, wsmu, wst, w, lane, Cg1);

  for (int t = 0; t < 256; t++) {
    const int pb = t & 1, nb = pb ^ 1;

    // head for t-1 (after bar2[t-1])
    if (t > 0) {
      bar_wait(barp + (t - 1) * 2 + 1);
      if (tid < 128) {
        const float* fp = &g_fcpart[(size_t)(bt * 128 + tid) * 32];
        float s = bfc;
#pragma unroll 8
        for (int k = 0; k < 32; k++) s += __ldcg(fp + k);
        float o = fmaxf(s, 0.f);
        osm[tid] = o;
        if (hs == 0) dout[(size_t)(bt * 128 + tid) * 256 + (t - 1)] = o;
      }
    }
    __syncthreads();

    // ---- cell-1 -> s0' ----
    {
      float ob[2] = {osm[blo], osm[blo + 8]};
#pragma unroll
      for (int bh = 0; bh < 2; bh++) {
#pragma unroll
        for (int i = 0; i < 4; i++) {
          int nt = i >> 1, e = bh * 2 + (i & 1);
          int hl = nt * 8 + h0 + (i & 1);
          float gr = yc[0][bh][i] + ob[bh] * btile[48 + hl] + Cg1[0][nt][e] + btile[hl];
          float gz = yc[1][bh][i] + ob[bh] * btile[64 + hl] + Cg1[1][nt][e] + btile[16 + hl];
          float gn = yc[2][bh][i] + ob[bh] * btile[80 + hl];
          float r = sigm(gr), z = sigm(gz);
          float n = tanh_(gn + r * (Cg1[2][nt][e] + btile[32 + hl]));
          s0f[bh][i] = (1.f - z) * n + z * s0f[bh][i];
        }
        int gb = bt * 128 + blo + bh * 8;
#pragma unroll
        for (int nt = 0; nt < 2; nt++)
          *(__half2*)&g_s0h[nb][(size_t)gb * 512 + hs * 16 + nt * 8 + h0] =
              __floats2half2_rn(s0f[bh][nt * 2], s0f[bh][nt * 2 + 1]);
      }
    }
    bar_arrive(barp + t * 2);  // s0' published

    // ---- gh2 = s1 @ whh2^T (hides bar1) ----
    gemm_slice(g_s1h[pb] + (size_t)bt * 65536, wsmu + 24576, wst, w, lane, Cg2);

    bar_wait(barp + t * 2);  // all s0' visible

    // ---- fused: gi2 (slice1) + gh1 for t+1 (slice0), one A pass ----
    gemm_dual(g_s0h[nb] + (size_t)bt * 65536, wsmu + 12288, wsmu, wst, w, lane,
              Ci, Cg1);

    // ---- cell-2 -> s1', fc partials ----
    {
#pragma unroll
      for (int bh = 0; bh < 2; bh++) {
        float p = 0.f;
#pragma unroll
        for (int i = 0; i < 4; i++) {
          int nt = i >> 1, e = bh * 2 + (i & 1);
          int hl = nt * 8 + h0 + (i & 1);
          float r = sigm(Ci[0][nt][e] + Cg2[0][nt][e] + btile[96 + hl]);
          float z = sigm(Ci[1][nt][e] + Cg2[1][nt][e] + btile[112 + hl]);
          float n = tanh_(Ci[2][nt][e] + btile[128 + hl] +
                          r * (Cg2[2][nt][e] + btile[144 + hl]));
          s1f[bh][i] = (1.f - z) * n + z * s1f[bh][i];
          p += s1f[bh][i] * btile[160 + hl];
        }
        int gb = bt * 128 + blo + bh * 8;
#pragma unroll
        for (int nt = 0; nt < 2; nt++)
          *(__half2*)&g_s1h[nb][(size_t)gb * 512 + hs * 16 + nt * 8 + h0] =
              __floats2half2_rn(s1f[bh][nt * 2], s1f[bh][nt * 2 + 1]);
        p += __shfl_xor_sync(0xffffffffu, p, 1);
        p += __shfl_xor_sync(0xffffffffu, p, 2);
        if ((lane & 3) == 0) __stcg(&g_fcpart[(size_t)gb * 32 + hs], p);
      }
    }
    bar_arrive(barp + t * 2 + 1);  // s1' + fcpart published
  }

  // final head (o[255])
  bar_wait(barp + 255 * 2 + 1);
  if (tid < 128 && hs == 0) {
    const float* fp = &g_fcpart[(size_t)(bt * 128 + tid) * 32];
    float s = bfc;
#pragma unroll 8
    for (int k = 0; k < 32; k++) s += __ldcg(fp + k);
    dout[(size_t)(bt * 128 + tid) * 256 + 255] = fmaxf(s, 0.f);
  }
}

}  // namespace

extern "C" void kernel_launch(void* const* d_in, const int* in_sizes, int n_in,
                              void* d_out, int out_size) {
  const float* z1   = (const float*)d_in[0];
  const float* y    = (const float*)d_in[1];
  const float* x    = (const float*)d_in[2];
  const float* h1   = (const float*)d_in[3];
  const float* wih1 = (const float*)d_in[4];
  const float* whh1 = (const float*)d_in[5];
  const float* bih1 = (const float*)d_in[6];
  const float* bhh1 = (const float*)d_in[7];
  const float* wih2 = (const float*)d_in[8];
  const float* whh2 = (const float*)d_in[9];
  const float* bih2 = (const float*)d_in[10];
  const float* bhh2 = (const float*)d_in[11];
  const float* wfc  = (const float*)d_in[12];
  const float* bfc  = (const float*)d_in[13];

  cudaFuncSetAttribute(gen_main, cudaFuncAttributeMaxDynamicSharedMemorySize,
                       SMEM_BYTES);

  prep_zero<<<16, 256>>>();
  prep_pack<<<2304, 256>>>(whh1, wih2, whh2);
  prep_yctr<<<512, 256>>>(y, wih1, bih1);
  gen_main<<<128, 256, SMEM_BYTES>>>(z1, y, x, h1, wih1, bhh1, bih2, bhh2,
                                     wfc, bfc, (float*)d_out);
}